// round 1
// baseline (speedup 1.0000x reference)
#include <cuda_runtime.h>

#define NPOS   65536
#define HW_    4096
#define KCB    4
#define SENT   1024
#define DIM    64
#define TILE_N 128
#define TILE_S 128
#define LDA    129
#define ZQ_ELEMS 16777216

// Scratch (no allocations allowed): entry norms, argmin indices, loss partials.
__device__ float  g_enorm[KCB * SENT];
__device__ int    g_idx[KCB * NPOS];
__device__ double g_part[KCB * (NPOS / 256)];

// ---------------------------------------------------------------------------
// ||e||^2 per codebook entry. Replicates reference: square rounded to fp32
// first (zf**2 is an elementwise op), then summed sequentially in fp32.
// ---------------------------------------------------------------------------
__global__ void enorm_kernel(const float* __restrict__ cb) {
    int j = blockIdx.x * 256 + threadIdx.x;   // 0..4095
    const float* e = cb + (size_t)j * DIM;
    float s = 0.f;
#pragma unroll
    for (int d = 0; d < DIM; d++) {
        float v = e[d];
        s = __fadd_rn(s, __fmul_rn(v, v));
    }
    g_enorm[j] = s;
}

// ---------------------------------------------------------------------------
// Fused distance-GEMM + argmin.
// Block: 256 threads = 16x16, each thread owns an 8x8 register tile.
// Tile: 128 positions x 128 codebook entries per chunk, 8 chunks over S=1024.
// dist = (znorm + enorm) - 2*dot   -- identical op/rounding order to the
// reference's  A + B - 2*einsum  elementwise expression.
// Tie-break: strict <  (within-thread j ascending) + lexicographic (dist, idx)
// cross-thread reduce == argmin's lowest-index semantics.
// ---------------------------------------------------------------------------
__global__ void __launch_bounds__(256, 2)
argmin_kernel(const float* __restrict__ z, const float* __restrict__ cb,
              float* __restrict__ out, int idx_off) {
    extern __shared__ float sm[];
    float* As = sm;                  // [DIM][LDA] z tile (loaded once)
    float* Bs = As + DIM * LDA;      // [DIM][LDA] codebook chunk
    float* zn = Bs + DIM * LDA;      // [TILE_N]
    float* en = zn + TILE_N;         // [TILE_S]

    const int k        = blockIdx.y;
    const int tileBase = blockIdx.x * TILE_N;
    const int b        = tileBase >> 12;          // HW_ = 4096
    const int hw0      = tileBase & (HW_ - 1);
    const int tid      = threadIdx.x;
    const int tx       = tid & 15;
    const int ty       = tid >> 4;

    // Load z tile: channels k*64..k*64+63 for 128 consecutive positions.
    // Global reads coalesced (contiguous hw per fixed channel); smem writes
    // conflict-free (stride LDA=129 -> bank = (d + i) distinct).
    const float* zbase = z + ((size_t)(b * 256 + k * DIM)) * HW_ + hw0;
    for (int i0 = tid; i0 < DIM * TILE_N; i0 += 256) {
        int d = i0 >> 7, i = i0 & 127;
        As[d * LDA + i] = zbase[(size_t)d * HW_ + i];
    }
    __syncthreads();

    // znorm per position: squares rounded, then sequential fp32 sum (d = 0..63).
    if (tid < TILE_N) {
        float s = 0.f;
        for (int d = 0; d < DIM; d++) {
            float v = As[d * LDA + tid];
            s = __fadd_rn(s, __fmul_rn(v, v));
        }
        zn[tid] = s;
    }

    float bestD[8];
    int   bestI[8];
#pragma unroll
    for (int u = 0; u < 8; u++) { bestD[u] = __int_as_float(0x7f800000); bestI[u] = 0; }

    const float* cbk = cb + (size_t)k * SENT * DIM;
    for (int chunk = 0; chunk < SENT / TILE_S; chunk++) {
        __syncthreads();
        // Load codebook chunk transposed into Bs[d][jj].
        const float* cbc = cbk + (size_t)chunk * TILE_S * DIM;
        for (int i0 = tid; i0 < TILE_S * DIM; i0 += 256) {
            int jj = i0 >> 6, d = i0 & 63;
            Bs[d * LDA + jj] = cbc[jj * DIM + d];
        }
        if (tid < TILE_S) en[tid] = g_enorm[k * SENT + chunk * TILE_S + tid];
        __syncthreads();

        float acc[8][8];
#pragma unroll
        for (int u = 0; u < 8; u++)
#pragma unroll
            for (int v = 0; v < 8; v++) acc[u][v] = 0.f;

        // Sequential FMA over d = 0..63 (matches fp32 FMA dot accumulation).
#pragma unroll 4
        for (int d = 0; d < DIM; d++) {
            float a[8], bfr[8];
#pragma unroll
            for (int u = 0; u < 8; u++) a[u]   = As[d * LDA + ty + 16 * u];
#pragma unroll
            for (int v = 0; v < 8; v++) bfr[v] = Bs[d * LDA + tx + 16 * v];
#pragma unroll
            for (int u = 0; u < 8; u++)
#pragma unroll
                for (int v = 0; v < 8; v++)
                    acc[u][v] = __fmaf_rn(a[u], bfr[v], acc[u][v]);
        }

        // dist = round(round(znorm + enorm) - 2*acc); 2*acc is exact.
#pragma unroll
        for (int u = 0; u < 8; u++) {
            float znu = zn[ty + 16 * u];
#pragma unroll
            for (int v = 0; v < 8; v++) {
                float t    = __fadd_rn(znu, en[tx + 16 * v]);
                float dist = __fsub_rn(t, __fmul_rn(2.0f, acc[u][v]));
                if (dist < bestD[u]) {
                    bestD[u] = dist;
                    bestI[u] = chunk * TILE_S + tx + 16 * v;  // ascending in v & chunk
                }
            }
        }
    }
    __syncthreads();

    // Cross-thread reduce: 16 tx partials per position, lexicographic (dist, idx).
    float* rd = As;                         // reuse: [TILE_N][16]
    int*   ri = (int*)(As + TILE_N * 16);   // [TILE_N][16]
#pragma unroll
    for (int u = 0; u < 8; u++) {
        int i = ty + 16 * u;
        rd[i * 16 + tx] = bestD[u];
        ri[i * 16 + tx] = bestI[u];
    }
    __syncthreads();
    if (tid < TILE_N) {
        float bd = rd[tid * 16];
        int   bi = ri[tid * 16];
#pragma unroll
        for (int t = 1; t < 16; t++) {
            float dd = rd[tid * 16 + t];
            int   ii = ri[tid * 16 + t];
            if (dd < bd || (dd == bd && ii < bi)) { bd = dd; bi = ii; }
        }
        int n = tileBase + tid;
        g_idx[k * NPOS + n] = bi;
        if (idx_off >= 0) out[(size_t)idx_off + k * NPOS + n] = (float)bi;
    }
}

// ---------------------------------------------------------------------------
// Gather codebook rows -> z_q (straight-through value == zq), plus
// deterministic per-block double partial sums of (zq - z)^2 for the loss.
// ---------------------------------------------------------------------------
__global__ void scatter_kernel(const float* __restrict__ z, const float* __restrict__ cb,
                               float* __restrict__ out) {
    const int k   = blockIdx.y;
    const int n   = blockIdx.x * 256 + threadIdx.x;
    const int idx = g_idx[k * NPOS + n];
    const int b   = n >> 12;
    const int hw  = n & (HW_ - 1);
    const float* crow = cb + ((size_t)(k * SENT + idx)) * DIM;
    const size_t base = ((size_t)(b * 256 + k * DIM)) * HW_ + hw;

    double local = 0.0;
#pragma unroll
    for (int d = 0; d < DIM; d++) {
        float val = __ldg(crow + d);
        float zv  = z[base + (size_t)d * HW_];
        out[base + (size_t)d * HW_] = val;       // coalesced across threads
        float diff = val - zv;
        local += (double)diff * (double)diff;
    }

    __shared__ double sred[256];
    sred[threadIdx.x] = local;
    __syncthreads();
    for (int s = 128; s > 0; s >>= 1) {
        if (threadIdx.x < s) sred[threadIdx.x] += sred[threadIdx.x + s];
        __syncthreads();
    }
    if (threadIdx.x == 0) g_part[k * (NPOS / 256) + blockIdx.x] = sred[0];
}

__global__ void finalize_kernel(float* __restrict__ out, int loss_off) {
    if (loss_off < 0) return;
    double s = 0.0;
    for (int i = 0; i < KCB * (NPOS / 256); i++) s += g_part[i];
    // total_loss = mean_k( mse_k + 0.25*mse_k ) = 1.25 * S_total / (K*N*d)
    out[loss_off] = (float)(1.25 * s / (double)ZQ_ELEMS);
}

// ---------------------------------------------------------------------------
extern "C" void kernel_launch(void* const* d_in, const int* in_sizes, int n_in,
                              void* d_out, int out_size) {
    const float* z  = (const float*)d_in[0];
    const float* cb = (const float*)d_in[1];
    if (n_in >= 2 && in_sizes[0] == KCB * SENT * DIM) {  // defensive: swapped order
        cb = (const float*)d_in[0];
        z  = (const float*)d_in[1];
    }
    float* out = (float*)d_out;

    // Output layout: [z_q (16777216)] [loss (1)] [indices (262144)] as f32.
    int loss_off = -1, idx_off = -1;
    if (out_size == ZQ_ELEMS + 1 + KCB * NPOS) { loss_off = ZQ_ELEMS; idx_off = ZQ_ELEMS + 1; }
    else if (out_size == ZQ_ELEMS + KCB * NPOS) { idx_off = ZQ_ELEMS; }

    const int smemBytes = (2 * DIM * LDA + TILE_N + TILE_S) * (int)sizeof(float);
    cudaFuncSetAttribute(argmin_kernel, cudaFuncAttributeMaxDynamicSharedMemorySize, smemBytes);

    enorm_kernel<<<KCB * SENT / 256, 256>>>(cb);

    dim3 ga(NPOS / TILE_N, KCB);
    argmin_kernel<<<ga, 256, smemBytes>>>(z, cb, out, idx_off);

    dim3 gs(NPOS / 256, KCB);
    scatter_kernel<<<gs, 256>>>(z, cb, out);

    finalize_kernel<<<1, 1>>>(out, loss_off);
}